// round 5
// baseline (speedup 1.0000x reference)
#include <cuda_runtime.h>
#include <math.h>

#define NPTS   8192
#define NPTOT  16384
#define KNBR   16
#define NTRI   (2*3*4096*64)
#define NCNT   (2*3*4096)
#define OUT_C   49152
#define OUT_TRI (49152 + 1048576)

__device__ float4 g_pts[NPTOT];          // x,y,z,|p|^2
__device__ int    g_idx[NPTOT*KNBR];
__device__ int    g_ij[NPTOT];
__device__ float  g_c[NPTOT*64];
__device__ float  g_x[NPTOT*32];
__device__ float  g_cnt[NCNT];
__device__ float  g_wt[5*16384];

// identical distance computation in both KNN passes (determinism-critical)
__device__ __forceinline__ float d2f(float qx,float qy,float qz,float qs, float4 c){
    float dot = fmaf(qx,c.x, fmaf(qy,c.y, qz*c.z));
    return fmaf(-2.0f, dot, qs + c.w);
}

// ---------------- stem + SoA + triplane cell indices ----------------
__global__ void k_stem(const float* __restrict__ xyz, const float* __restrict__ ws,
                       const float* __restrict__ bs) {
    int gid = blockIdx.x*blockDim.x + threadIdx.x;
    if (gid >= NPTOT*64) return;
    int p = gid >> 6, d = gid & 63;
    float x = xyz[p*3+0], y = xyz[p*3+1], z = xyz[p*3+2];
    g_c[gid] = fmaf(z, ws[128+d], fmaf(y, ws[64+d], fmaf(x, ws[d], bs[d])));
    if (d == 0) {
        g_pts[p] = make_float4(x, y, z, fmaf(z, z, fmaf(y, y, x*x)));
        const float den = 1.101f;
        float px = x/den + 0.5f, py = y/den + 0.5f, pz = z/den + 0.5f;
        int ix = (int)(px*64.0f); ix = min(max(ix,0),63);
        int iy = (int)(py*64.0f); iy = min(max(iy,0),63);
        int iz = (int)(pz*64.0f); iz = min(max(iz,0),63);
        g_ij[p] = ix | (iy<<6) | (iz<<12);
    }
}

// ---------------- wcv transpose: [o][c][s] -> [c*16+s][o] per block ----------------
__global__ void k_wt(const float* __restrict__ wcv) {
    int gid = blockIdx.x*blockDim.x + threadIdx.x;
    if (gid >= 5*16384) return;
    int blk = gid / 16384, r = gid % 16384;
    int o = r >> 9, c = (r >> 4) & 31, s = r & 15;
    g_wt[blk*16384 + (c*16+s)*32 + o] = wcv[gid];
}

// ---------------- exact KNN: warp = 4 queries, two-pass threshold ----------------
#define KCAP 96
#define QW   4
#define KWPB 8
#define KQPB (QW*KWPB)

__global__ void __launch_bounds__(256) k_knn() {
    __shared__ float bufd[KQPB][KCAP];
    __shared__ int   bufi[KQPB][KCAP];
    __shared__ int   bcnt[KQPB];

    const int tid = threadIdx.x, w = tid >> 5, lane = tid & 31;
    const int p0 = blockIdx.x*KQPB + w*QW;
    const int base = (p0 >> 13) * NPTS;
    const float4* __restrict__ pts = g_pts + base;

    float4 Q0 = g_pts[p0+0], Q1 = g_pts[p0+1], Q2 = g_pts[p0+2], Q3 = g_pts[p0+3];
    if (lane < QW) bcnt[w*QW + lane] = 0;

    float m0 = 1e30f, m1 = 1e30f, m2 = 1e30f, m3 = 1e30f;
    #pragma unroll 4
    for (int i = 0; i < NPTS/32; i++) {
        float4 c = pts[i*32 + lane];
        m0 = fminf(m0, d2f(Q0.x,Q0.y,Q0.z,Q0.w, c));
        m1 = fminf(m1, d2f(Q1.x,Q1.y,Q1.z,Q1.w, c));
        m2 = fminf(m2, d2f(Q2.x,Q2.y,Q2.z,Q2.w, c));
        m3 = fminf(m3, d2f(Q3.x,Q3.y,Q3.z,Q3.w, c));
    }

    float T0, T1, T2, T3;
    #pragma unroll
    for (int q = 0; q < QW; q++) {
        float vv = (q==0) ? m0 : (q==1) ? m1 : (q==2) ? m2 : m3;
        float T = 0.f;
        for (int r = 0; r < 16; r++) {
            float mv = vv; int ml = lane;
            #pragma unroll
            for (int off = 16; off; off >>= 1) {
                float ov = __shfl_xor_sync(0xffffffffu, mv, off);
                int   ol = __shfl_xor_sync(0xffffffffu, ml, off);
                if (ov < mv || (ov == mv && ol < ml)) { mv = ov; ml = ol; }
            }
            T = mv;
            if (lane == ml) vv = 1e30f;
        }
        if (q==0) T0=T; else if (q==1) T1=T; else if (q==2) T2=T; else T3=T;
    }
    __syncwarp();

    #pragma unroll 2
    for (int i = 0; i < NPTS/32; i++) {
        int j = i*32 + lane;
        float4 c = pts[j];
        float d0 = d2f(Q0.x,Q0.y,Q0.z,Q0.w, c);
        float d1 = d2f(Q1.x,Q1.y,Q1.z,Q1.w, c);
        float d2v = d2f(Q2.x,Q2.y,Q2.z,Q2.w, c);
        float d3 = d2f(Q3.x,Q3.y,Q3.z,Q3.w, c);
        if (d0 <= T0) { int pos = atomicAdd(&bcnt[w*QW+0],1); if (pos<KCAP){bufd[w*QW+0][pos]=d0; bufi[w*QW+0][pos]=j;} }
        if (d1 <= T1) { int pos = atomicAdd(&bcnt[w*QW+1],1); if (pos<KCAP){bufd[w*QW+1][pos]=d1; bufi[w*QW+1][pos]=j;} }
        if (d2v <= T2){ int pos = atomicAdd(&bcnt[w*QW+2],1); if (pos<KCAP){bufd[w*QW+2][pos]=d2v;bufi[w*QW+2][pos]=j;} }
        if (d3 <= T3) { int pos = atomicAdd(&bcnt[w*QW+3],1); if (pos<KCAP){bufd[w*QW+3][pos]=d3; bufi[w*QW+3][pos]=j;} }
    }
    __syncwarp();

    for (int q = 0; q < QW; q++) {
        int wq = w*QW + q;
        int cnt = bcnt[wq];
        int p = p0 + q;
        if (cnt <= KCAP) {
            for (int r = 0; r < KNBR; r++) {
                float lbd = 1e30f; int lbi = 0x7fffffff; int lpos = -1;
                for (int j = lane; j < cnt; j += 32) {
                    float d = bufd[wq][j]; int ii = bufi[wq][j];
                    if (d < lbd || (d == lbd && ii < lbi)) { lbd = d; lbi = ii; lpos = j; }
                }
                float bd = lbd; int bi = lbi;
                #pragma unroll
                for (int off = 16; off; off >>= 1) {
                    float od = __shfl_xor_sync(0xffffffffu, bd, off);
                    int   oi = __shfl_xor_sync(0xffffffffu, bi, off);
                    if (od < bd || (od == bd && oi < bi)) { bd = od; bi = oi; }
                }
                if (lpos >= 0 && lbi == bi) bufd[wq][lpos] = 1e30f;
                if (lane == 0) g_idx[p*KNBR + r] = base + bi;
                __syncwarp();
            }
        } else if (lane == 0) {
            float4 Q = (q==0)?Q0:(q==1)?Q1:(q==2)?Q2:Q3;
            float td[KNBR]; int ti[KNBR];
            #pragma unroll
            for (int r = 0; r < KNBR; r++) { td[r] = 1e30f; ti[r] = 0x7fffffff; }
            for (int m = 0; m < NPTS; m++) {
                float dd = d2f(Q.x,Q.y,Q.z,Q.w, pts[m]);
                if (dd < td[KNBR-1] || (dd == td[KNBR-1] && m < ti[KNBR-1])) {
                    float cd = dd; int ci = m;
                    #pragma unroll
                    for (int r = 0; r < KNBR; r++) {
                        bool lt = (cd < td[r]) || (cd == td[r] && ci < ti[r]);
                        if (lt) { float t1=td[r]; int t2=ti[r]; td[r]=cd; ti[r]=ci; cd=t1; ci=t2; }
                    }
                }
            }
            for (int r = 0; r < KNBR; r++) g_idx[p*KNBR + r] = base + ti[r];
        }
        __syncwarp();
    }
}

// ---------------- x = relu(c @ w0 + b0) ----------------
__global__ void k_xup(const float* __restrict__ w0, const float* __restrict__ b0) {
    int gid = blockIdx.x*blockDim.x + threadIdx.x;
    if (gid >= NPTOT*32) return;
    int n = gid >> 5, h = gid & 31;
    const float* cr = g_c + n*64;
    float a0 = b0[h], a1 = 0.f;
    #pragma unroll
    for (int d = 0; d < 64; d += 2) {
        a0 = fmaf(cr[d],   w0[d*32+h],     a0);
        a1 = fmaf(cr[d+1], w0[(d+1)*32+h], a1);
    }
    g_x[gid] = fmaxf(a0 + a1, 0.f);
}

// ---------------- fused FKAConv + w2 + residual; CTA = 16 points, wcv in smem ----------------
// dynamic smem layout (floats):
//   swcv[16384] | sfc1[48] | sfc2[512] | sfc3[512] | sM[4096] | sF[8192] | sR[512] | sI[256 ints]
#define FKA_SMEM_FLOATS (16384 + 48 + 512 + 512 + 4096 + 8192 + 512 + 256)
#define FKA_SMEM_BYTES  (FKA_SMEM_FLOATS * 4)

__global__ void __launch_bounds__(256) k_fka(int blk, int last,
    const float* __restrict__ fc1, const float* __restrict__ fc2,
    const float* __restrict__ fc3, const float* __restrict__ alpha,
    const float* __restrict__ beta, const float* __restrict__ w2,
    const float* __restrict__ b2, float* __restrict__ outc)
{
    extern __shared__ float smem[];
    float* swcv = smem;
    float* sfc1 = swcv + 16384;
    float* sfc2 = sfc1 + 48;
    float* sfc3 = sfc2 + 512;
    float* sM   = sfc3 + 512;    // [pt 0..15][k][s]
    float* sF   = sM + 4096;     // [pt][cs]
    float* sR   = sF + 8192;     // [pt][o]
    int*   sI   = (int*)(sR + 512); // [pt][k]

    int tid = threadIdx.x, w = tid >> 5, lane = tid & 31;

    // cooperative loads: wcv (64KB, float4) + MLP weights
    {
        const float4* src = (const float4*)(g_wt + blk*16384);
        float4* dst = (float4*)swcv;
        #pragma unroll
        for (int i = tid; i < 4096; i += 256) dst[i] = src[i];
    }
    for (int i = tid; i < 48;  i += 256) sfc1[i] = fc1[i];
    for (int i = tid; i < 512; i += 256) { sfc2[i] = fc2[i]; sfc3[i] = fc3[i]; }
    __syncthreads();

    int half = lane >> 4, k = lane & 15;
    int lp = w*2 + half;                    // local point 0..15
    int p = blockIdx.x*16 + lp;
    int ik = g_idx[p*KNBR + k];
    sI[lp*16 + k] = ik;
    float4 q  = g_pts[p];
    float4 nb = g_pts[ik];
    float dx = nb.x-q.x, dy = nb.y-q.y, dz = nb.z-q.z;
    float dist = sqrtf(dx*dx + dy*dy + dz*dz + 1e-12f);
    float zz = beta[0] - alpha[0]*dist;
    float dwr = 1.0f/(1.0f + expf(-zz));
    float sm = dwr;
    #pragma unroll
    for (int off = 8; off; off >>= 1) sm += __shfl_xor_sync(0xffffffffu, sm, off);
    float dw = dwr / (sm + 1e-6f) * 16.0f;

    float a[16], b[16], c2[16];
    #pragma unroll
    for (int s = 0; s < 16; s++)
        a[s] = fmaxf(fmaf(dx, sfc1[s], fmaf(dy, sfc1[16+s], dz*sfc1[32+s])), 0.f);
    #pragma unroll
    for (int s = 0; s < 16; s++) {
        float v = a[s]*dw;
        #pragma unroll
        for (int off = 8; off; off >>= 1) v = fmaxf(v, __shfl_xor_sync(0xffffffffu, v, off));
        b[s] = v;
    }
    #pragma unroll
    for (int s = 0; s < 16; s++) c2[s] = 0.f;
    #pragma unroll 4
    for (int r = 0; r < 16; r++) {
        float va = a[r], vb = b[r];
        #pragma unroll
        for (int s = 0; s < 16; s++)
            c2[s] = fmaf(va, sfc2[r*16+s], fmaf(vb, sfc2[(16+r)*16+s], c2[s]));
    }
    #pragma unroll
    for (int s = 0; s < 16; s++) a[s] = fmaxf(c2[s], 0.f);
    #pragma unroll
    for (int s = 0; s < 16; s++) {
        float v = a[s]*dw;
        #pragma unroll
        for (int off = 8; off; off >>= 1) v = fmaxf(v, __shfl_xor_sync(0xffffffffu, v, off));
        b[s] = v;
    }
    #pragma unroll
    for (int s = 0; s < 16; s++) c2[s] = 0.f;
    #pragma unroll 4
    for (int r = 0; r < 16; r++) {
        float va = a[r], vb = b[r];
        #pragma unroll
        for (int s = 0; s < 16; s++)
            c2[s] = fmaf(va, sfc3[r*16+s], fmaf(vb, sfc3[(16+r)*16+s], c2[s]));
    }
    {   // m = relu(m3)*dw -> smem
        float4* md = (float4*)&sM[(lp*16 + k)*16];
        md[0] = make_float4(fmaxf(c2[0],0.f)*dw, fmaxf(c2[1],0.f)*dw,
                            fmaxf(c2[2],0.f)*dw, fmaxf(c2[3],0.f)*dw);
        md[1] = make_float4(fmaxf(c2[4],0.f)*dw, fmaxf(c2[5],0.f)*dw,
                            fmaxf(c2[6],0.f)*dw, fmaxf(c2[7],0.f)*dw);
        md[2] = make_float4(fmaxf(c2[8],0.f)*dw, fmaxf(c2[9],0.f)*dw,
                            fmaxf(c2[10],0.f)*dw, fmaxf(c2[11],0.f)*dw);
        md[3] = make_float4(fmaxf(c2[12],0.f)*dw, fmaxf(c2[13],0.f)*dw,
                            fmaxf(c2[14],0.f)*dw, fmaxf(c2[15],0.f)*dw);
    }
    __syncwarp();

    // f[c][s] = sum_k nb_x[k][c]*m[k][s]; lane = c
    #pragma unroll
    for (int pt = 0; pt < 2; pt++) {
        int lpt = w*2 + pt;
        float f[16];
        #pragma unroll
        for (int s = 0; s < 16; s++) f[s] = 0.f;
        const int* ip = &sI[lpt*16];
        #pragma unroll 4
        for (int kk = 0; kk < 16; kk++) {
            float nbx = g_x[ip[kk]*32 + lane];
            const float4* mv = (const float4*)&sM[(lpt*16 + kk)*16];
            float4 v0 = mv[0], v1 = mv[1], v2 = mv[2], v3 = mv[3];
            f[0]=fmaf(nbx,v0.x,f[0]);  f[1]=fmaf(nbx,v0.y,f[1]);
            f[2]=fmaf(nbx,v0.z,f[2]);  f[3]=fmaf(nbx,v0.w,f[3]);
            f[4]=fmaf(nbx,v1.x,f[4]);  f[5]=fmaf(nbx,v1.y,f[5]);
            f[6]=fmaf(nbx,v1.z,f[6]);  f[7]=fmaf(nbx,v1.w,f[7]);
            f[8]=fmaf(nbx,v2.x,f[8]);  f[9]=fmaf(nbx,v2.y,f[9]);
            f[10]=fmaf(nbx,v2.z,f[10]); f[11]=fmaf(nbx,v2.w,f[11]);
            f[12]=fmaf(nbx,v3.x,f[12]); f[13]=fmaf(nbx,v3.y,f[13]);
            f[14]=fmaf(nbx,v3.z,f[14]); f[15]=fmaf(nbx,v3.w,f[15]);
        }
        float4* fd = (float4*)&sF[lpt*512 + lane*16];
        fd[0] = make_float4(f[0],f[1],f[2],f[3]);
        fd[1] = make_float4(f[4],f[5],f[6],f[7]);
        fd[2] = make_float4(f[8],f[9],f[10],f[11]);
        fd[3] = make_float4(f[12],f[13],f[14],f[15]);
    }
    __syncwarp();

    // out[o] = sum_cs f[cs]*swcv[cs][o]; lane owns an o-quad, 2 points per warp
    {
        int csoff = lane >> 3, o0 = (lane & 7) << 2;
        const float* fA = &sF[(w*2+0)*512];
        const float* fB = &sF[(w*2+1)*512];
        float aA0=0,aA1=0,aA2=0,aA3=0, aB0=0,aB1=0,aB2=0,aB3=0;
        #pragma unroll 8
        for (int g2 = 0; g2 < 128; g2++) {
            int cs = (g2<<2) + csoff;
            float4 wv = *(const float4*)(swcv + (cs<<5) + o0);
            float fa = fA[cs], fb = fB[cs];
            aA0=fmaf(fa,wv.x,aA0); aA1=fmaf(fa,wv.y,aA1);
            aA2=fmaf(fa,wv.z,aA2); aA3=fmaf(fa,wv.w,aA3);
            aB0=fmaf(fb,wv.x,aB0); aB1=fmaf(fb,wv.y,aB1);
            aB2=fmaf(fb,wv.z,aB2); aB3=fmaf(fb,wv.w,aB3);
        }
        #pragma unroll
        for (int off = 8; off <= 16; off <<= 1) {
            aA0 += __shfl_xor_sync(0xffffffffu, aA0, off);
            aA1 += __shfl_xor_sync(0xffffffffu, aA1, off);
            aA2 += __shfl_xor_sync(0xffffffffu, aA2, off);
            aA3 += __shfl_xor_sync(0xffffffffu, aA3, off);
            aB0 += __shfl_xor_sync(0xffffffffu, aB0, off);
            aB1 += __shfl_xor_sync(0xffffffffu, aB1, off);
            aB2 += __shfl_xor_sync(0xffffffffu, aB2, off);
            aB3 += __shfl_xor_sync(0xffffffffu, aB3, off);
        }
        if (lane < 8) {
            float* rA = &sR[(w*2+0)*32 + o0];
            float* rB = &sR[(w*2+1)*32 + o0];
            rA[0]=fmaxf(aA0,0.f); rA[1]=fmaxf(aA1,0.f); rA[2]=fmaxf(aA2,0.f); rA[3]=fmaxf(aA3,0.f);
            rB[0]=fmaxf(aB0,0.f); rB[1]=fmaxf(aB1,0.f); rB[2]=fmaxf(aB2,0.f); rB[3]=fmaxf(aB3,0.f);
        }
    }
    __syncwarp();

    // c = relu(r @ w2 + b2 + c); lane handles d=lane and d=lane+32
    int d0 = lane, d1 = lane + 32;
    #pragma unroll
    for (int pt = 0; pt < 2; pt++) {
        int lpt = w*2 + pt;
        int p2 = blockIdx.x*16 + lpt;
        float acc0 = b2[d0], acc1 = b2[d1];
        const float* rr = &sR[lpt*32];
        #pragma unroll 8
        for (int h = 0; h < 32; h++) {
            float rh = rr[h];
            acc0 = fmaf(rh, w2[h*64 + d0], acc0);
            acc1 = fmaf(rh, w2[h*64 + d1], acc1);
        }
        float c0 = g_c[p2*64 + d0], c1 = g_c[p2*64 + d1];
        float v0 = fmaxf(acc0 + c0, 0.f), v1 = fmaxf(acc1 + c1, 0.f);
        g_c[p2*64 + d0] = v0;
        g_c[p2*64 + d1] = v1;
        if (last) { outc[p2*64 + d0] = v0; outc[p2*64 + d1] = v1; }
    }
}

// ---------------- triplane ----------------
__global__ void k_zero(float* __restrict__ tri) {
    int gid = blockIdx.x*blockDim.x + threadIdx.x;
    if (gid < NTRI) tri[gid] = 0.f;
    if (gid < NCNT) g_cnt[gid] = 0.f;
}
__global__ void k_scatter(float* __restrict__ tri) {
    int gid = blockIdx.x*blockDim.x + threadIdx.x;
    if (gid >= NPTOT*64) return;
    int p = gid >> 6, d = gid & 63;
    int code = g_ij[p];
    int i0 = code & 63, i1 = (code>>6)&63, i2 = (code>>12)&63;
    int base = (p >> 13) * 3 * 4096;
    int c01 = base + (i0*64+i1);
    int c02 = base + 4096 + (i0*64+i2);
    int c12 = base + 8192 + (i1*64+i2);
    float v = g_c[gid];
    atomicAdd(&tri[c01*64 + d], v);
    atomicAdd(&tri[c02*64 + d], v);
    atomicAdd(&tri[c12*64 + d], v);
    if (d == 0) {
        atomicAdd(&g_cnt[c01], 1.f);
        atomicAdd(&g_cnt[c02], 1.f);
        atomicAdd(&g_cnt[c12], 1.f);
    }
}
__global__ void k_norm(float* __restrict__ tri) {
    int gid = blockIdx.x*blockDim.x + threadIdx.x;
    if (gid >= NTRI) return;
    tri[gid] = tri[gid] / fmaxf(g_cnt[gid >> 6], 1.f);
}

extern "C" void kernel_launch(void* const* d_in, const int* in_sizes, int n_in,
                              void* d_out, int out_size) {
    const float* xyz    = (const float*)d_in[0];
    const float* w_stem = (const float*)d_in[1];
    const float* b_stem = (const float*)d_in[2];
    const float* w0     = (const float*)d_in[3];
    const float* b0     = (const float*)d_in[4];
    const float* fc1    = (const float*)d_in[5];
    const float* fc2    = (const float*)d_in[6];
    const float* fc3    = (const float*)d_in[7];
    const float* wcv    = (const float*)d_in[8];
    const float* alpha  = (const float*)d_in[9];
    const float* beta   = (const float*)d_in[10];
    const float* w2     = (const float*)d_in[11];
    const float* b2     = (const float*)d_in[12];
    float* out = (float*)d_out;

    static int smem_set = 0;
    if (!smem_set) {
        cudaFuncSetAttribute(k_fka, cudaFuncAttributeMaxDynamicSharedMemorySize,
                             FKA_SMEM_BYTES);
        smem_set = 1;
    }

    k_stem<<<4096, 256>>>(xyz, w_stem, b_stem);
    k_wt<<<320, 256>>>(wcv);
    k_zero<<<6144, 256>>>(out + OUT_TRI);
    cudaMemcpyAsync(out, xyz, NPTOT*3*sizeof(float), cudaMemcpyDeviceToDevice, 0);
    k_knn<<<NPTOT/KQPB, 256>>>();
    for (int i = 0; i < 5; i++) {
        k_xup<<<2048, 256>>>(w0 + i*2048, b0 + i*32);
        k_fka<<<1024, 256, FKA_SMEM_BYTES>>>(i, (i == 4) ? 1 : 0,
                             fc1 + i*48, fc2 + i*512, fc3 + i*512,
                             alpha + i, beta + i, w2 + i*2048, b2 + i*64,
                             out + OUT_C);
    }
    k_scatter<<<4096, 256>>>(out + OUT_TRI);
    k_norm<<<6144, 256>>>(out + OUT_TRI);
}

// round 6
// speedup vs baseline: 1.1212x; 1.1212x over previous
#include <cuda_runtime.h>
#include <math.h>

#define NPTS   8192
#define NPTOT  16384
#define KNBR   16
#define NTRI   (2*3*4096*64)
#define NCNT   (2*3*4096)
#define OUT_C   49152
#define OUT_TRI (49152 + 1048576)

__device__ float4 g_pts[NPTOT];          // x,y,z,|p|^2
__device__ int    g_idx[NPTOT*KNBR];
__device__ int    g_ij[NPTOT];
__device__ float  g_c[NPTOT*64];
__device__ float  g_x[NPTOT*32];
__device__ float  g_cnt[NCNT];
__device__ float  g_wt[5*16384];

// identical distance computation in both KNN passes (determinism-critical)
__device__ __forceinline__ float d2f(float qx,float qy,float qz,float qs, float4 c){
    float dot = fmaf(qx,c.x, fmaf(qy,c.y, qz*c.z));
    return fmaf(-2.0f, dot, qs + c.w);
}

// ---------------- stem + SoA + triplane cell indices ----------------
__global__ void k_stem(const float* __restrict__ xyz, const float* __restrict__ ws,
                       const float* __restrict__ bs) {
    int gid = blockIdx.x*blockDim.x + threadIdx.x;
    if (gid >= NPTOT*64) return;
    int p = gid >> 6, d = gid & 63;
    float x = xyz[p*3+0], y = xyz[p*3+1], z = xyz[p*3+2];
    g_c[gid] = fmaf(z, ws[128+d], fmaf(y, ws[64+d], fmaf(x, ws[d], bs[d])));
    if (d == 0) {
        g_pts[p] = make_float4(x, y, z, fmaf(z, z, fmaf(y, y, x*x)));
        const float den = 1.101f;
        float px = x/den + 0.5f, py = y/den + 0.5f, pz = z/den + 0.5f;
        int ix = (int)(px*64.0f); ix = min(max(ix,0),63);
        int iy = (int)(py*64.0f); iy = min(max(iy,0),63);
        int iz = (int)(pz*64.0f); iz = min(max(iz,0),63);
        g_ij[p] = ix | (iy<<6) | (iz<<12);
    }
}

// ---------------- wcv transpose: [o][c][s] -> [c*16+s][o] per block ----------------
__global__ void k_wt(const float* __restrict__ wcv) {
    int gid = blockIdx.x*blockDim.x + threadIdx.x;
    if (gid >= 5*16384) return;
    int blk = gid / 16384, r = gid % 16384;
    int o = r >> 9, c = (r >> 4) & 31, s = r & 15;
    g_wt[blk*16384 + (c*16+s)*32 + o] = wcv[gid];
}

// ---------------- exact KNN: warp = 4 queries, two-pass threshold ----------------
#define KCAP 96
#define QW   4
#define KWPB 8
#define KQPB (QW*KWPB)

__global__ void __launch_bounds__(256, 4) k_knn() {
    __shared__ float bufd[KQPB][KCAP];
    __shared__ int   bufi[KQPB][KCAP];
    __shared__ int   bcnt[KQPB];

    const int tid = threadIdx.x, w = tid >> 5, lane = tid & 31;
    const int p0 = blockIdx.x*KQPB + w*QW;
    const int base = (p0 >> 13) * NPTS;
    const float4* __restrict__ pts = g_pts + base;

    float4 Q0 = g_pts[p0+0], Q1 = g_pts[p0+1], Q2 = g_pts[p0+2], Q3 = g_pts[p0+3];
    if (lane < QW) bcnt[w*QW + lane] = 0;

    // pass 1: per-lane minimum over its 256-candidate partition, x4 queries
    float m0 = 1e30f, m1 = 1e30f, m2 = 1e30f, m3 = 1e30f;
    #pragma unroll 2
    for (int i = 0; i < NPTS/32; i++) {
        float4 c = pts[i*32 + lane];
        m0 = fminf(m0, d2f(Q0.x,Q0.y,Q0.z,Q0.w, c));
        m1 = fminf(m1, d2f(Q1.x,Q1.y,Q1.z,Q1.w, c));
        m2 = fminf(m2, d2f(Q2.x,Q2.y,Q2.z,Q2.w, c));
        m3 = fminf(m3, d2f(Q3.x,Q3.y,Q3.z,Q3.w, c));
    }

    // T[q] = 16th smallest of the 32 lane-minima
    float T0, T1, T2, T3;
    #pragma unroll
    for (int q = 0; q < QW; q++) {
        float vv = (q==0) ? m0 : (q==1) ? m1 : (q==2) ? m2 : m3;
        float T = 0.f;
        for (int r = 0; r < 16; r++) {
            float mv = vv; int ml = lane;
            #pragma unroll
            for (int off = 16; off; off >>= 1) {
                float ov = __shfl_xor_sync(0xffffffffu, mv, off);
                int   ol = __shfl_xor_sync(0xffffffffu, ml, off);
                if (ov < mv || (ov == mv && ol < ml)) { mv = ov; ml = ol; }
            }
            T = mv;
            if (lane == ml) vv = 1e30f;
        }
        if (q==0) T0=T; else if (q==1) T1=T; else if (q==2) T2=T; else T3=T;
    }
    __syncwarp();

    // pass 2: collect survivors (identical arithmetic -> threshold exact)
    #pragma unroll 2
    for (int i = 0; i < NPTS/32; i++) {
        int j = i*32 + lane;
        float4 c = pts[j];
        float d0 = d2f(Q0.x,Q0.y,Q0.z,Q0.w, c);
        float d1 = d2f(Q1.x,Q1.y,Q1.z,Q1.w, c);
        float d2v = d2f(Q2.x,Q2.y,Q2.z,Q2.w, c);
        float d3 = d2f(Q3.x,Q3.y,Q3.z,Q3.w, c);
        if (d0 <= T0) { int pos = atomicAdd(&bcnt[w*QW+0],1); if (pos<KCAP){bufd[w*QW+0][pos]=d0; bufi[w*QW+0][pos]=j;} }
        if (d1 <= T1) { int pos = atomicAdd(&bcnt[w*QW+1],1); if (pos<KCAP){bufd[w*QW+1][pos]=d1; bufi[w*QW+1][pos]=j;} }
        if (d2v <= T2){ int pos = atomicAdd(&bcnt[w*QW+2],1); if (pos<KCAP){bufd[w*QW+2][pos]=d2v;bufi[w*QW+2][pos]=j;} }
        if (d3 <= T3) { int pos = atomicAdd(&bcnt[w*QW+3],1); if (pos<KCAP){bufd[w*QW+3][pos]=d3; bufi[w*QW+3][pos]=j;} }
    }
    __syncwarp();

    // per query: 16 lexicographic (d2, idx) min-extractions (matches top_k ties)
    for (int q = 0; q < QW; q++) {
        int wq = w*QW + q;
        int cnt = bcnt[wq];
        int p = p0 + q;
        if (cnt <= KCAP) {
            for (int r = 0; r < KNBR; r++) {
                float lbd = 1e30f; int lbi = 0x7fffffff; int lpos = -1;
                for (int j = lane; j < cnt; j += 32) {
                    float d = bufd[wq][j]; int ii = bufi[wq][j];
                    if (d < lbd || (d == lbd && ii < lbi)) { lbd = d; lbi = ii; lpos = j; }
                }
                float bd = lbd; int bi = lbi;
                #pragma unroll
                for (int off = 16; off; off >>= 1) {
                    float od = __shfl_xor_sync(0xffffffffu, bd, off);
                    int   oi = __shfl_xor_sync(0xffffffffu, bi, off);
                    if (od < bd || (od == bd && oi < bi)) { bd = od; bi = oi; }
                }
                if (lpos >= 0 && lbi == bi) bufd[wq][lpos] = 1e30f;
                if (lane == 0) g_idx[p*KNBR + r] = base + bi;
                __syncwarp();
            }
        } else if (lane == 0) {     // pathological overflow: serial exact
            float4 Q = (q==0)?Q0:(q==1)?Q1:(q==2)?Q2:Q3;
            float td[KNBR]; int ti[KNBR];
            #pragma unroll
            for (int r = 0; r < KNBR; r++) { td[r] = 1e30f; ti[r] = 0x7fffffff; }
            for (int m = 0; m < NPTS; m++) {
                float dd = d2f(Q.x,Q.y,Q.z,Q.w, pts[m]);
                if (dd < td[KNBR-1] || (dd == td[KNBR-1] && m < ti[KNBR-1])) {
                    float cd = dd; int ci = m;
                    #pragma unroll
                    for (int r = 0; r < KNBR; r++) {
                        bool lt = (cd < td[r]) || (cd == td[r] && ci < ti[r]);
                        if (lt) { float t1=td[r]; int t2=ti[r]; td[r]=cd; ti[r]=ci; cd=t1; ci=t2; }
                    }
                }
            }
            for (int r = 0; r < KNBR; r++) g_idx[p*KNBR + r] = base + ti[r];
        }
        __syncwarp();
    }
}

// ---------------- x = relu(c @ w0 + b0) ----------------
__global__ void k_xup(const float* __restrict__ w0, const float* __restrict__ b0) {
    int gid = blockIdx.x*blockDim.x + threadIdx.x;
    if (gid >= NPTOT*32) return;
    int n = gid >> 5, h = gid & 31;
    const float* cr = g_c + n*64;
    float a0 = b0[h], a1 = 0.f;
    #pragma unroll
    for (int d = 0; d < 64; d += 2) {
        a0 = fmaf(cr[d],   w0[d*32+h],     a0);
        a1 = fmaf(cr[d+1], w0[(d+1)*32+h], a1);
    }
    g_x[gid] = fmaxf(a0 + a1, 0.f);
}

// ---------------- fused FKAConv + w2 + residual; warp = 2 points (round-4 shape) ----------------
__global__ void __launch_bounds__(128) k_fka(int blk, int last,
    const float* __restrict__ fc1, const float* __restrict__ fc2,
    const float* __restrict__ fc3, const float* __restrict__ alpha,
    const float* __restrict__ beta, const float* __restrict__ w2,
    const float* __restrict__ b2, float* __restrict__ outc)
{
    __shared__ float sfc1[48], sfc2[512], sfc3[512];
    __shared__ float sM[2048];   // [warp][pt][k][s]
    __shared__ float sF[4096];   // [warp][pt][cs]
    __shared__ float sR[256];    // [warp][pt][o]
    __shared__ int   sI[128];    // [warp][pt][k]

    int tid = threadIdx.x, w = tid >> 5, lane = tid & 31;
    for (int i = tid; i < 48;  i += 128) sfc1[i] = fc1[i];
    for (int i = tid; i < 512; i += 128) { sfc2[i] = fc2[i]; sfc3[i] = fc3[i]; }
    __syncthreads();

    int half = lane >> 4, k = lane & 15;
    int p = blockIdx.x*8 + w*2 + half;
    int ik = g_idx[p*KNBR + k];
    sI[(w*2+half)*16 + k] = ik;
    float4 q  = g_pts[p];
    float4 nb = g_pts[ik];
    float dx = nb.x-q.x, dy = nb.y-q.y, dz = nb.z-q.z;
    float dist = sqrtf(dx*dx + dy*dy + dz*dz + 1e-12f);
    float zz = beta[0] - alpha[0]*dist;
    float dwr = 1.0f/(1.0f + expf(-zz));
    float sm = dwr;
    #pragma unroll
    for (int off = 8; off; off >>= 1) sm += __shfl_xor_sync(0xffffffffu, sm, off);
    float dw = dwr / (sm + 1e-6f) * 16.0f;

    float a[16], b[16], c2[16];
    #pragma unroll
    for (int s = 0; s < 16; s++)
        a[s] = fmaxf(fmaf(dx, sfc1[s], fmaf(dy, sfc1[16+s], dz*sfc1[32+s])), 0.f);
    #pragma unroll
    for (int s = 0; s < 16; s++) {
        float v = a[s]*dw;
        #pragma unroll
        for (int off = 8; off; off >>= 1) v = fmaxf(v, __shfl_xor_sync(0xffffffffu, v, off));
        b[s] = v;
    }
    #pragma unroll
    for (int s = 0; s < 16; s++) c2[s] = 0.f;
    #pragma unroll 4
    for (int r = 0; r < 16; r++) {
        float va = a[r], vb = b[r];
        #pragma unroll
        for (int s = 0; s < 16; s++)
            c2[s] = fmaf(va, sfc2[r*16+s], fmaf(vb, sfc2[(16+r)*16+s], c2[s]));
    }
    #pragma unroll
    for (int s = 0; s < 16; s++) a[s] = fmaxf(c2[s], 0.f);
    #pragma unroll
    for (int s = 0; s < 16; s++) {
        float v = a[s]*dw;
        #pragma unroll
        for (int off = 8; off; off >>= 1) v = fmaxf(v, __shfl_xor_sync(0xffffffffu, v, off));
        b[s] = v;
    }
    #pragma unroll
    for (int s = 0; s < 16; s++) c2[s] = 0.f;
    #pragma unroll 4
    for (int r = 0; r < 16; r++) {
        float va = a[r], vb = b[r];
        #pragma unroll
        for (int s = 0; s < 16; s++)
            c2[s] = fmaf(va, sfc3[r*16+s], fmaf(vb, sfc3[(16+r)*16+s], c2[s]));
    }
    {   // m = relu(m3)*dw -> smem
        float4* md = (float4*)&sM[((w*2+half)*16 + k)*16];
        md[0] = make_float4(fmaxf(c2[0],0.f)*dw, fmaxf(c2[1],0.f)*dw,
                            fmaxf(c2[2],0.f)*dw, fmaxf(c2[3],0.f)*dw);
        md[1] = make_float4(fmaxf(c2[4],0.f)*dw, fmaxf(c2[5],0.f)*dw,
                            fmaxf(c2[6],0.f)*dw, fmaxf(c2[7],0.f)*dw);
        md[2] = make_float4(fmaxf(c2[8],0.f)*dw, fmaxf(c2[9],0.f)*dw,
                            fmaxf(c2[10],0.f)*dw, fmaxf(c2[11],0.f)*dw);
        md[3] = make_float4(fmaxf(c2[12],0.f)*dw, fmaxf(c2[13],0.f)*dw,
                            fmaxf(c2[14],0.f)*dw, fmaxf(c2[15],0.f)*dw);
    }
    __syncwarp();

    // f[c][s] = sum_k nb_x[k][c]*m[k][s]; lane = c
    #pragma unroll
    for (int pt = 0; pt < 2; pt++) {
        float f[16];
        #pragma unroll
        for (int s = 0; s < 16; s++) f[s] = 0.f;
        const int* ip = &sI[(w*2+pt)*16];
        #pragma unroll 4
        for (int kk = 0; kk < 16; kk++) {
            float nbx = g_x[ip[kk]*32 + lane];
            const float4* mv = (const float4*)&sM[((w*2+pt)*16 + kk)*16];
            float4 v0 = mv[0], v1 = mv[1], v2 = mv[2], v3 = mv[3];
            f[0]=fmaf(nbx,v0.x,f[0]);  f[1]=fmaf(nbx,v0.y,f[1]);
            f[2]=fmaf(nbx,v0.z,f[2]);  f[3]=fmaf(nbx,v0.w,f[3]);
            f[4]=fmaf(nbx,v1.x,f[4]);  f[5]=fmaf(nbx,v1.y,f[5]);
            f[6]=fmaf(nbx,v1.z,f[6]);  f[7]=fmaf(nbx,v1.w,f[7]);
            f[8]=fmaf(nbx,v2.x,f[8]);  f[9]=fmaf(nbx,v2.y,f[9]);
            f[10]=fmaf(nbx,v2.z,f[10]); f[11]=fmaf(nbx,v2.w,f[11]);
            f[12]=fmaf(nbx,v3.x,f[12]); f[13]=fmaf(nbx,v3.y,f[13]);
            f[14]=fmaf(nbx,v3.z,f[14]); f[15]=fmaf(nbx,v3.w,f[15]);
        }
        float4* fd = (float4*)&sF[(w*2+pt)*512 + lane*16];
        fd[0] = make_float4(f[0],f[1],f[2],f[3]);
        fd[1] = make_float4(f[4],f[5],f[6],f[7]);
        fd[2] = make_float4(f[8],f[9],f[10],f[11]);
        fd[3] = make_float4(f[12],f[13],f[14],f[15]);
    }
    __syncwarp();

    // out[o] = sum_cs f[cs]*wt[cs][o]; lane owns an o-quad (wcv L1-resident)
    {
        int csoff = lane >> 3, o0 = (lane & 7) << 2;
        const float* wtb = g_wt + blk*16384;
        const float* fA = &sF[(w*2+0)*512];
        const float* fB = &sF[(w*2+1)*512];
        float aA0=0,aA1=0,aA2=0,aA3=0, aB0=0,aB1=0,aB2=0,aB3=0;
        #pragma unroll 8
        for (int g2 = 0; g2 < 128; g2++) {
            int cs = (g2<<2) + csoff;
            float4 wv = *(const float4*)(wtb + (cs<<5) + o0);
            float fa = fA[cs], fb = fB[cs];
            aA0=fmaf(fa,wv.x,aA0); aA1=fmaf(fa,wv.y,aA1);
            aA2=fmaf(fa,wv.z,aA2); aA3=fmaf(fa,wv.w,aA3);
            aB0=fmaf(fb,wv.x,aB0); aB1=fmaf(fb,wv.y,aB1);
            aB2=fmaf(fb,wv.z,aB2); aB3=fmaf(fb,wv.w,aB3);
        }
        #pragma unroll
        for (int off = 8; off <= 16; off <<= 1) {
            aA0 += __shfl_xor_sync(0xffffffffu, aA0, off);
            aA1 += __shfl_xor_sync(0xffffffffu, aA1, off);
            aA2 += __shfl_xor_sync(0xffffffffu, aA2, off);
            aA3 += __shfl_xor_sync(0xffffffffu, aA3, off);
            aB0 += __shfl_xor_sync(0xffffffffu, aB0, off);
            aB1 += __shfl_xor_sync(0xffffffffu, aB1, off);
            aB2 += __shfl_xor_sync(0xffffffffu, aB2, off);
            aB3 += __shfl_xor_sync(0xffffffffu, aB3, off);
        }
        if (lane < 8) {
            float* rA = &sR[(w*2+0)*32 + o0];
            float* rB = &sR[(w*2+1)*32 + o0];
            rA[0]=fmaxf(aA0,0.f); rA[1]=fmaxf(aA1,0.f); rA[2]=fmaxf(aA2,0.f); rA[3]=fmaxf(aA3,0.f);
            rB[0]=fmaxf(aB0,0.f); rB[1]=fmaxf(aB1,0.f); rB[2]=fmaxf(aB2,0.f); rB[3]=fmaxf(aB3,0.f);
        }
    }
    __syncwarp();

    // c = relu(r @ w2 + b2 + c); lane handles d=lane and d=lane+32
    int d0 = lane, d1 = lane + 32;
    #pragma unroll
    for (int pt = 0; pt < 2; pt++) {
        int p2 = blockIdx.x*8 + w*2 + pt;
        float acc0 = b2[d0], acc1 = b2[d1];
        const float* rr = &sR[(w*2+pt)*32];
        #pragma unroll 8
        for (int h = 0; h < 32; h++) {
            float rh = rr[h];
            acc0 = fmaf(rh, w2[h*64 + d0], acc0);
            acc1 = fmaf(rh, w2[h*64 + d1], acc1);
        }
        float c0 = g_c[p2*64 + d0], c1 = g_c[p2*64 + d1];
        float v0 = fmaxf(acc0 + c0, 0.f), v1 = fmaxf(acc1 + c1, 0.f);
        g_c[p2*64 + d0] = v0;
        g_c[p2*64 + d1] = v1;
        if (last) { outc[p2*64 + d0] = v0; outc[p2*64 + d1] = v1; }
    }
}

// ---------------- triplane ----------------
__global__ void k_zero(float* __restrict__ tri) {
    int gid = blockIdx.x*blockDim.x + threadIdx.x;
    if (gid < NTRI) tri[gid] = 0.f;
    if (gid < NCNT) g_cnt[gid] = 0.f;
}
__global__ void k_scatter(float* __restrict__ tri) {
    int gid = blockIdx.x*blockDim.x + threadIdx.x;
    if (gid >= NPTOT*64) return;
    int p = gid >> 6, d = gid & 63;
    int code = g_ij[p];
    int i0 = code & 63, i1 = (code>>6)&63, i2 = (code>>12)&63;
    int base = (p >> 13) * 3 * 4096;
    int c01 = base + (i0*64+i1);
    int c02 = base + 4096 + (i0*64+i2);
    int c12 = base + 8192 + (i1*64+i2);
    float v = g_c[gid];
    atomicAdd(&tri[c01*64 + d], v);
    atomicAdd(&tri[c02*64 + d], v);
    atomicAdd(&tri[c12*64 + d], v);
    if (d == 0) {
        atomicAdd(&g_cnt[c01], 1.f);
        atomicAdd(&g_cnt[c02], 1.f);
        atomicAdd(&g_cnt[c12], 1.f);
    }
}
__global__ void k_norm(float* __restrict__ tri) {
    int gid = blockIdx.x*blockDim.x + threadIdx.x;
    if (gid >= NTRI) return;
    tri[gid] = tri[gid] / fmaxf(g_cnt[gid >> 6], 1.f);
}

extern "C" void kernel_launch(void* const* d_in, const int* in_sizes, int n_in,
                              void* d_out, int out_size) {
    const float* xyz    = (const float*)d_in[0];
    const float* w_stem = (const float*)d_in[1];
    const float* b_stem = (const float*)d_in[2];
    const float* w0     = (const float*)d_in[3];
    const float* b0     = (const float*)d_in[4];
    const float* fc1    = (const float*)d_in[5];
    const float* fc2    = (const float*)d_in[6];
    const float* fc3    = (const float*)d_in[7];
    const float* wcv    = (const float*)d_in[8];
    const float* alpha  = (const float*)d_in[9];
    const float* beta   = (const float*)d_in[10];
    const float* w2     = (const float*)d_in[11];
    const float* b2     = (const float*)d_in[12];
    float* out = (float*)d_out;

    k_stem<<<4096, 256>>>(xyz, w_stem, b_stem);
    k_wt<<<320, 256>>>(wcv);
    k_zero<<<6144, 256>>>(out + OUT_TRI);
    cudaMemcpyAsync(out, xyz, NPTOT*3*sizeof(float), cudaMemcpyDeviceToDevice, 0);
    k_knn<<<NPTOT/KQPB, 256>>>();
    for (int i = 0; i < 5; i++) {
        k_xup<<<2048, 256>>>(w0 + i*2048, b0 + i*32);
        k_fka<<<2048, 128>>>(i, (i == 4) ? 1 : 0,
                             fc1 + i*48, fc2 + i*512, fc3 + i*512,
                             alpha + i, beta + i, w2 + i*2048, b2 + i*64,
                             out + OUT_C);
    }
    k_scatter<<<4096, 256>>>(out + OUT_TRI);
    k_norm<<<6144, 256>>>(out + OUT_TRI);
}